// round 14
// baseline (speedup 1.0000x reference)
#include <cuda_runtime.h>
#include <cuda_bf16.h>
#include <cstdint>

// BinaryTimedPSP: out[t] = clip(causal boxcar sum width d, 0, 1).
// Binary spikes => out[t] = 1 iff any spike in [t-d+1, t].
//
// Two-pass, phase-pure, PDL-overlapped. Measured-optimal configuration:
//   P1: x -> per-(segment, component) 64-bit spike masks (256MB read, 8MB write)
//       8 back-to-back LDG.128 forced via asm volatile, BLOCK=128.
//   P2: masks (+ parallel bounded lookback, L2-hot) -> output bits -> stores,
//       BLOCK=128 (best measured pass2 block size; 256 was 1-3us slower).

#define TDIM    2048
#define SEG     32
#define SEG_LEN 64
#define BLOCK1  128
#define BLOCK2  128
#define MAXC    8192          // max float4 column-groups (B*N/4)
#define BIGAGE  (1u << 20)

__device__ ulonglong4 g_mask[SEG * MAXC];   // 8 MiB

__device__ __forceinline__ unsigned long long window_or(unsigned long long s, unsigned d) {
    unsigned long long r = s;
    unsigned w = 1;
    while (w < d && w < 64u) {
        unsigned sh = d - w;
        if (sh > w) sh = w;
        r |= r << sh;
        w += sh;
    }
    return r;
}
__device__ __forceinline__ unsigned long long prefix_mask(unsigned len) {
    return (len >= 64u) ? ~0ull : ((1ull << len) - 1ull);
}
__device__ __forceinline__ unsigned load_d(const int* durp) {
    unsigned d = 100;
    if (durp) {
        int dv = *durp;
        if (dv > 0 && dv <= TDIM * 16) d = (unsigned)dv;
    }
    return d;
}

// v is 0x00000000 (0.0f) or 0x3F800000 (1.0f). Move bit 23 to bit t, masked.
__device__ __forceinline__ unsigned spikebit(unsigned v, int t) {
    unsigned sh = (t <= 23) ? (v >> (23 - t)) : (v << (t - 23));
    return sh & (1u << t);
}

__device__ __forceinline__ void ldg128_cs(const uint4* p,
                                          unsigned& a, unsigned& b,
                                          unsigned& c, unsigned& d) {
    asm volatile("ld.global.cs.v4.u32 {%0,%1,%2,%3}, [%4];"
                 : "=r"(a), "=r"(b), "=r"(c), "=r"(d) : "l"(p));
}

// ---- Pass 1: build spike masks (forced 8-deep load batches) ----
__global__ __launch_bounds__(BLOCK1) void psp_pass1(
    const uint4* __restrict__ x, int row4)
{
    const int c = blockIdx.x * BLOCK1 + threadIdx.x;
    const int s = blockIdx.y;
    if (c < row4) {
        const uint4* __restrict__ xp = x + (size_t)(s * SEG_LEN) * row4 + c;

        unsigned lo0 = 0, lo1 = 0, lo2 = 0, lo3 = 0;
        unsigned hi0 = 0, hi1 = 0, hi2 = 0, hi3 = 0;
        #pragma unroll
        for (int tb = 0; tb < SEG_LEN; tb += 8) {
            unsigned v[8][4];
            // 8 consecutive volatile loads: ptxas cannot sink/serialize them.
            #pragma unroll
            for (int k = 0; k < 8; ++k)
                ldg128_cs(&xp[(size_t)(tb + k) * row4],
                          v[k][0], v[k][1], v[k][2], v[k][3]);
            #pragma unroll
            for (int k = 0; k < 8; ++k) {
                const int t = tb + k;
                if (t < 32) {
                    lo0 |= spikebit(v[k][0], t);
                    lo1 |= spikebit(v[k][1], t);
                    lo2 |= spikebit(v[k][2], t);
                    lo3 |= spikebit(v[k][3], t);
                } else {
                    hi0 |= spikebit(v[k][0], t - 32);
                    hi1 |= spikebit(v[k][1], t - 32);
                    hi2 |= spikebit(v[k][2], t - 32);
                    hi3 |= spikebit(v[k][3], t - 32);
                }
            }
        }
        ulonglong4 m;
        m.x = (unsigned long long)lo0 | ((unsigned long long)hi0 << 32);
        m.y = (unsigned long long)lo1 | ((unsigned long long)hi1 << 32);
        m.z = (unsigned long long)lo2 | ((unsigned long long)hi2 << 32);
        m.w = (unsigned long long)lo3 | ((unsigned long long)hi3 << 32);
        g_mask[s * MAXC + c] = m;
    }
    // make mask stores visible, then let the dependent grid proceed
    __threadfence();
    cudaTriggerProgrammaticLaunchCompletion();
}

// ---- Pass 2: parallel bounded lookback + window-OR + streaming stores ----
__global__ __launch_bounds__(BLOCK2) void psp_pass2(
    float4* __restrict__ out, const int* __restrict__ durp, int row4)
{
    const int c = blockIdx.x * BLOCK2 + threadIdx.x;
    const int s = blockIdx.y;
    // prologue overlapped with pass1 (durp is harness input, stable pre-graph)
    const unsigned d = load_d(durp);
    float4* __restrict__ op = out + (size_t)(s * SEG_LEN) * row4 + c;

    cudaGridDependencySynchronize();
    if (c >= row4) return;

    // issue all (up to 3) mask loads in parallel: own + 2 predecessors
    ulonglong4 m = g_mask[s * MAXC + c];
    ulonglong4 pm1 = {0, 0, 0, 0}, pm2 = {0, 0, 0, 0};
    if (s >= 1)            pm1 = g_mask[(s - 1) * MAXC + c];
    if (s >= 2 && d > 65u) pm2 = g_mask[(s - 2) * MAXC + c];

    uint4 inc;
    inc.x = pm1.x ? (unsigned)__clzll(pm1.x) : (pm2.x ? 64u + (unsigned)__clzll(pm2.x) : BIGAGE);
    inc.y = pm1.y ? (unsigned)__clzll(pm1.y) : (pm2.y ? 64u + (unsigned)__clzll(pm2.y) : BIGAGE);
    inc.z = pm1.z ? (unsigned)__clzll(pm1.z) : (pm2.z ? 64u + (unsigned)__clzll(pm2.z) : BIGAGE);
    inc.w = pm1.w ? (unsigned)__clzll(pm1.w) : (pm2.w ? 64u + (unsigned)__clzll(pm2.w) : BIGAGE);

    if (d > 129u) {   // rare general case: continue lookback past 2 segments
        unsigned base = 128;
        for (int j = s - 3; j >= 0 && base + 1u < d; --j) {
            if (inc.x != BIGAGE && inc.y != BIGAGE && inc.z != BIGAGE && inc.w != BIGAGE)
                break;
            ulonglong4 pm = g_mask[j * MAXC + c];
            if (inc.x == BIGAGE && pm.x) inc.x = base + (unsigned)__clzll(pm.x);
            if (inc.y == BIGAGE && pm.y) inc.y = base + (unsigned)__clzll(pm.y);
            if (inc.z == BIGAGE && pm.z) inc.z = base + (unsigned)__clzll(pm.z);
            if (inc.w == BIGAGE && pm.w) inc.w = base + (unsigned)__clzll(pm.w);
            base += SEG_LEN;
        }
    }

    unsigned long long b0 = window_or(m.x, d);
    unsigned long long b1 = window_or(m.y, d);
    unsigned long long b2 = window_or(m.z, d);
    unsigned long long b3 = window_or(m.w, d);

    // prefix fix: bits t < min(first_spike, d-1-inc) forced to 1
    unsigned p0 = m.x ? (unsigned)(__ffsll((long long)m.x) - 1) : 64u;
    unsigned p1 = m.y ? (unsigned)(__ffsll((long long)m.y) - 1) : 64u;
    unsigned p2 = m.z ? (unsigned)(__ffsll((long long)m.z) - 1) : 64u;
    unsigned p3 = m.w ? (unsigned)(__ffsll((long long)m.w) - 1) : 64u;
    unsigned l0 = (inc.x + 1u < d) ? min(p0, d - 1u - inc.x) : 0u;
    unsigned l1 = (inc.y + 1u < d) ? min(p1, d - 1u - inc.y) : 0u;
    unsigned l2 = (inc.z + 1u < d) ? min(p2, d - 1u - inc.z) : 0u;
    unsigned l3 = (inc.w + 1u < d) ? min(p3, d - 1u - inc.w) : 0u;
    b0 |= prefix_mask(l0);
    b1 |= prefix_mask(l1);
    b2 |= prefix_mask(l2);
    b3 |= prefix_mask(l3);

    const unsigned a0 = (unsigned)b0, A0 = (unsigned)(b0 >> 32);
    const unsigned a1 = (unsigned)b1, A1 = (unsigned)(b1 >> 32);
    const unsigned a2 = (unsigned)b2, A2 = (unsigned)(b2 >> 32);
    const unsigned a3 = (unsigned)b3, A3 = (unsigned)(b3 >> 32);

    #pragma unroll
    for (int t = 0; t < 32; ++t) {
        float4 o;
        o.x = __uint_as_float((unsigned)(((int)(a0 << (31 - t))) >> 31) & 0x3F800000u);
        o.y = __uint_as_float((unsigned)(((int)(a1 << (31 - t))) >> 31) & 0x3F800000u);
        o.z = __uint_as_float((unsigned)(((int)(a2 << (31 - t))) >> 31) & 0x3F800000u);
        o.w = __uint_as_float((unsigned)(((int)(a3 << (31 - t))) >> 31) & 0x3F800000u);
        __stcs(&op[(size_t)t * row4], o);
    }
    #pragma unroll
    for (int t = 0; t < 32; ++t) {
        float4 o;
        o.x = __uint_as_float((unsigned)(((int)(A0 << (31 - t))) >> 31) & 0x3F800000u);
        o.y = __uint_as_float((unsigned)(((int)(A1 << (31 - t))) >> 31) & 0x3F800000u);
        o.z = __uint_as_float((unsigned)(((int)(A2 << (31 - t))) >> 31) & 0x3F800000u);
        o.w = __uint_as_float((unsigned)(((int)(A3 << (31 - t))) >> 31) & 0x3F800000u);
        __stcs(&op[(size_t)(t + 32) * row4], o);
    }
}

// ---- Fallback (odd shapes): halo scan ----
__global__ __launch_bounds__(128) void psp_scan_kernel(
    const float4* __restrict__ x, float4* __restrict__ out,
    const int* __restrict__ durp, int row4, int T, int seg_len)
{
    const int c = blockIdx.x * 128 + threadIdx.x;
    if (c >= row4) return;
    int d = 100;
    if (durp) { int dv = *durp; if (dv > 0 && dv <= T * 16) d = dv; }
    const int t0 = blockIdx.y * seg_len;
    int th = t0 - (d - 1); if (th < 0) th = 0;
    int ax = 1 << 28, ay = 1 << 28, az = 1 << 28, aw = 1 << 28;
    for (int t = th; t < t0; ++t) {
        float4 v = x[(size_t)t * row4 + c];
        ax = (v.x != 0.0f) ? 0 : ax + 1; ay = (v.y != 0.0f) ? 0 : ay + 1;
        az = (v.z != 0.0f) ? 0 : az + 1; aw = (v.w != 0.0f) ? 0 : aw + 1;
    }
    int tend = t0 + seg_len; if (tend > T) tend = T;
    for (int t = t0; t < tend; ++t) {
        float4 v = x[(size_t)t * row4 + c];
        ax = (v.x != 0.0f) ? 0 : ax + 1; ay = (v.y != 0.0f) ? 0 : ay + 1;
        az = (v.z != 0.0f) ? 0 : az + 1; aw = (v.w != 0.0f) ? 0 : aw + 1;
        float4 o;
        o.x = (ax < d) ? 1.0f : 0.0f; o.y = (ay < d) ? 1.0f : 0.0f;
        o.z = (az < d) ? 1.0f : 0.0f; o.w = (aw < d) ? 1.0f : 0.0f;
        out[(size_t)t * row4 + c] = o;
    }
}

extern "C" void kernel_launch(void* const* d_in, const int* in_sizes, int n_in,
                              void* d_out, int out_size)
{
    const float* x = (const float*)d_in[0];
    const int* durp = (n_in > 1) ? (const int*)d_in[1] : nullptr;
    float* out = (float*)d_out;

    const int total = in_sizes[0];
    const int T = TDIM;
    const int row = total / T;
    const int row4 = row / 4;

    if ((row % 4 == 0) && (row4 <= MAXC) && (total == T * row)) {
        const int gx1 = (row4 + BLOCK1 - 1) / BLOCK1;
        psp_pass1<<<dim3(gx1, SEG), BLOCK1>>>((const uint4*)x, row4);

        // pass2 with programmatic dependent launch (overlap ramp with pass1 tail)
        cudaLaunchConfig_t cfg = {};
        cfg.gridDim  = dim3((row4 + BLOCK2 - 1) / BLOCK2, SEG, 1);
        cfg.blockDim = dim3(BLOCK2, 1, 1);
        cfg.dynamicSmemBytes = 0;
        cfg.stream = 0;
        cudaLaunchAttribute attr[1];
        attr[0].id = cudaLaunchAttributeProgrammaticStreamSerialization;
        attr[0].val.programmaticStreamSerializationAllowed = 1;
        cfg.attrs = attr;
        cfg.numAttrs = 1;
        cudaError_t e = cudaLaunchKernelEx(&cfg, psp_pass2,
                                           (float4*)out, (const int*)durp, row4);
        if (e != cudaSuccess) {   // PDL unavailable: plain launch
            psp_pass2<<<cfg.gridDim, cfg.blockDim>>>((float4*)out, durp, row4);
        }
    } else {
        const int seg = 8, seg_len = (T + seg - 1) / seg;
        dim3 grid((row4 + 127) / 128, seg);
        psp_scan_kernel<<<grid, 128>>>((const float4*)x, (float4*)out,
                                       durp, row4, T, seg_len);
    }
}

// round 15
// speedup vs baseline: 1.0172x; 1.0172x over previous
#include <cuda_runtime.h>
#include <cuda_bf16.h>
#include <cstdint>

// BinaryTimedPSP: out[t] = clip(causal boxcar sum width d, 0, 1).
// Binary spikes => out[t] = 1 iff any spike in [t-d+1, t].
//
// FINAL: two-pass, phase-pure, PDL-overlapped. This configuration sits at the
// measured DRAM floor (~92us = 268MB read @5.9 + 276MB write @6.0 TB/s + 2us).
// All structural departures benched slower (R9-R14): fused read/write kernel
// (mixed streams run 5.2 TB/s aggregate), 16-deep batches, rolling pipelines,
// BLOCK1=256; pass2 block size is noise.
//   P1: x -> per-(segment, component) 64-bit spike masks (256MB read, 8MB write)
//       8 back-to-back LDG.128 forced via asm volatile, BLOCK=128.
//   P2: masks (+ parallel bounded lookback, L2-hot) -> output bits -> stores.

#define TDIM    2048
#define SEG     32
#define SEG_LEN 64
#define BLOCK1  128
#define BLOCK2  256
#define MAXC    8192          // max float4 column-groups (B*N/4)
#define BIGAGE  (1u << 20)

__device__ ulonglong4 g_mask[SEG * MAXC];   // 8 MiB

__device__ __forceinline__ unsigned long long window_or(unsigned long long s, unsigned d) {
    unsigned long long r = s;
    unsigned w = 1;
    while (w < d && w < 64u) {
        unsigned sh = d - w;
        if (sh > w) sh = w;
        r |= r << sh;
        w += sh;
    }
    return r;
}
__device__ __forceinline__ unsigned long long prefix_mask(unsigned len) {
    return (len >= 64u) ? ~0ull : ((1ull << len) - 1ull);
}
__device__ __forceinline__ unsigned load_d(const int* durp) {
    unsigned d = 100;
    if (durp) {
        int dv = *durp;
        if (dv > 0 && dv <= TDIM * 16) d = (unsigned)dv;
    }
    return d;
}

// v is 0x00000000 (0.0f) or 0x3F800000 (1.0f). Move bit 23 to bit t, masked.
__device__ __forceinline__ unsigned spikebit(unsigned v, int t) {
    unsigned sh = (t <= 23) ? (v >> (23 - t)) : (v << (t - 23));
    return sh & (1u << t);
}

__device__ __forceinline__ void ldg128_cs(const uint4* p,
                                          unsigned& a, unsigned& b,
                                          unsigned& c, unsigned& d) {
    asm volatile("ld.global.cs.v4.u32 {%0,%1,%2,%3}, [%4];"
                 : "=r"(a), "=r"(b), "=r"(c), "=r"(d) : "l"(p));
}

// ---- Pass 1: build spike masks (forced 8-deep load batches) ----
__global__ __launch_bounds__(BLOCK1) void psp_pass1(
    const uint4* __restrict__ x, int row4)
{
    const int c = blockIdx.x * BLOCK1 + threadIdx.x;
    const int s = blockIdx.y;
    if (c < row4) {
        const uint4* __restrict__ xp = x + (size_t)(s * SEG_LEN) * row4 + c;

        unsigned lo0 = 0, lo1 = 0, lo2 = 0, lo3 = 0;
        unsigned hi0 = 0, hi1 = 0, hi2 = 0, hi3 = 0;
        #pragma unroll
        for (int tb = 0; tb < SEG_LEN; tb += 8) {
            unsigned v[8][4];
            // 8 consecutive volatile loads: ptxas cannot sink/serialize them.
            #pragma unroll
            for (int k = 0; k < 8; ++k)
                ldg128_cs(&xp[(size_t)(tb + k) * row4],
                          v[k][0], v[k][1], v[k][2], v[k][3]);
            #pragma unroll
            for (int k = 0; k < 8; ++k) {
                const int t = tb + k;
                if (t < 32) {
                    lo0 |= spikebit(v[k][0], t);
                    lo1 |= spikebit(v[k][1], t);
                    lo2 |= spikebit(v[k][2], t);
                    lo3 |= spikebit(v[k][3], t);
                } else {
                    hi0 |= spikebit(v[k][0], t - 32);
                    hi1 |= spikebit(v[k][1], t - 32);
                    hi2 |= spikebit(v[k][2], t - 32);
                    hi3 |= spikebit(v[k][3], t - 32);
                }
            }
        }
        ulonglong4 m;
        m.x = (unsigned long long)lo0 | ((unsigned long long)hi0 << 32);
        m.y = (unsigned long long)lo1 | ((unsigned long long)hi1 << 32);
        m.z = (unsigned long long)lo2 | ((unsigned long long)hi2 << 32);
        m.w = (unsigned long long)lo3 | ((unsigned long long)hi3 << 32);
        g_mask[s * MAXC + c] = m;
    }
    // make mask stores visible, then let the dependent grid proceed
    __threadfence();
    cudaTriggerProgrammaticLaunchCompletion();
}

// ---- Pass 2: parallel bounded lookback + window-OR + streaming stores ----
__global__ __launch_bounds__(BLOCK2) void psp_pass2(
    float4* __restrict__ out, const int* __restrict__ durp, int row4)
{
    const int c = blockIdx.x * BLOCK2 + threadIdx.x;
    const int s = blockIdx.y;
    // prologue overlapped with pass1 (durp is harness input, stable pre-graph)
    const unsigned d = load_d(durp);
    float4* __restrict__ op = out + (size_t)(s * SEG_LEN) * row4 + c;

    cudaGridDependencySynchronize();
    if (c >= row4) return;

    // issue all (up to 3) mask loads in parallel: own + 2 predecessors
    ulonglong4 m = g_mask[s * MAXC + c];
    ulonglong4 pm1 = {0, 0, 0, 0}, pm2 = {0, 0, 0, 0};
    if (s >= 1)            pm1 = g_mask[(s - 1) * MAXC + c];
    if (s >= 2 && d > 65u) pm2 = g_mask[(s - 2) * MAXC + c];

    uint4 inc;
    inc.x = pm1.x ? (unsigned)__clzll(pm1.x) : (pm2.x ? 64u + (unsigned)__clzll(pm2.x) : BIGAGE);
    inc.y = pm1.y ? (unsigned)__clzll(pm1.y) : (pm2.y ? 64u + (unsigned)__clzll(pm2.y) : BIGAGE);
    inc.z = pm1.z ? (unsigned)__clzll(pm1.z) : (pm2.z ? 64u + (unsigned)__clzll(pm2.z) : BIGAGE);
    inc.w = pm1.w ? (unsigned)__clzll(pm1.w) : (pm2.w ? 64u + (unsigned)__clzll(pm2.w) : BIGAGE);

    if (d > 129u) {   // rare general case: continue lookback past 2 segments
        unsigned base = 128;
        for (int j = s - 3; j >= 0 && base + 1u < d; --j) {
            if (inc.x != BIGAGE && inc.y != BIGAGE && inc.z != BIGAGE && inc.w != BIGAGE)
                break;
            ulonglong4 pm = g_mask[j * MAXC + c];
            if (inc.x == BIGAGE && pm.x) inc.x = base + (unsigned)__clzll(pm.x);
            if (inc.y == BIGAGE && pm.y) inc.y = base + (unsigned)__clzll(pm.y);
            if (inc.z == BIGAGE && pm.z) inc.z = base + (unsigned)__clzll(pm.z);
            if (inc.w == BIGAGE && pm.w) inc.w = base + (unsigned)__clzll(pm.w);
            base += SEG_LEN;
        }
    }

    unsigned long long b0 = window_or(m.x, d);
    unsigned long long b1 = window_or(m.y, d);
    unsigned long long b2 = window_or(m.z, d);
    unsigned long long b3 = window_or(m.w, d);

    // prefix fix: bits t < min(first_spike, d-1-inc) forced to 1
    unsigned p0 = m.x ? (unsigned)(__ffsll((long long)m.x) - 1) : 64u;
    unsigned p1 = m.y ? (unsigned)(__ffsll((long long)m.y) - 1) : 64u;
    unsigned p2 = m.z ? (unsigned)(__ffsll((long long)m.z) - 1) : 64u;
    unsigned p3 = m.w ? (unsigned)(__ffsll((long long)m.w) - 1) : 64u;
    unsigned l0 = (inc.x + 1u < d) ? min(p0, d - 1u - inc.x) : 0u;
    unsigned l1 = (inc.y + 1u < d) ? min(p1, d - 1u - inc.y) : 0u;
    unsigned l2 = (inc.z + 1u < d) ? min(p2, d - 1u - inc.z) : 0u;
    unsigned l3 = (inc.w + 1u < d) ? min(p3, d - 1u - inc.w) : 0u;
    b0 |= prefix_mask(l0);
    b1 |= prefix_mask(l1);
    b2 |= prefix_mask(l2);
    b3 |= prefix_mask(l3);

    const unsigned a0 = (unsigned)b0, A0 = (unsigned)(b0 >> 32);
    const unsigned a1 = (unsigned)b1, A1 = (unsigned)(b1 >> 32);
    const unsigned a2 = (unsigned)b2, A2 = (unsigned)(b2 >> 32);
    const unsigned a3 = (unsigned)b3, A3 = (unsigned)(b3 >> 32);

    #pragma unroll
    for (int t = 0; t < 32; ++t) {
        float4 o;
        o.x = __uint_as_float((unsigned)(((int)(a0 << (31 - t))) >> 31) & 0x3F800000u);
        o.y = __uint_as_float((unsigned)(((int)(a1 << (31 - t))) >> 31) & 0x3F800000u);
        o.z = __uint_as_float((unsigned)(((int)(a2 << (31 - t))) >> 31) & 0x3F800000u);
        o.w = __uint_as_float((unsigned)(((int)(a3 << (31 - t))) >> 31) & 0x3F800000u);
        __stcs(&op[(size_t)t * row4], o);
    }
    #pragma unroll
    for (int t = 0; t < 32; ++t) {
        float4 o;
        o.x = __uint_as_float((unsigned)(((int)(A0 << (31 - t))) >> 31) & 0x3F800000u);
        o.y = __uint_as_float((unsigned)(((int)(A1 << (31 - t))) >> 31) & 0x3F800000u);
        o.z = __uint_as_float((unsigned)(((int)(A2 << (31 - t))) >> 31) & 0x3F800000u);
        o.w = __uint_as_float((unsigned)(((int)(A3 << (31 - t))) >> 31) & 0x3F800000u);
        __stcs(&op[(size_t)(t + 32) * row4], o);
    }
}

// ---- Fallback (odd shapes): halo scan ----
__global__ __launch_bounds__(128) void psp_scan_kernel(
    const float4* __restrict__ x, float4* __restrict__ out,
    const int* __restrict__ durp, int row4, int T, int seg_len)
{
    const int c = blockIdx.x * 128 + threadIdx.x;
    if (c >= row4) return;
    int d = 100;
    if (durp) { int dv = *durp; if (dv > 0 && dv <= T * 16) d = dv; }
    const int t0 = blockIdx.y * seg_len;
    int th = t0 - (d - 1); if (th < 0) th = 0;
    int ax = 1 << 28, ay = 1 << 28, az = 1 << 28, aw = 1 << 28;
    for (int t = th; t < t0; ++t) {
        float4 v = x[(size_t)t * row4 + c];
        ax = (v.x != 0.0f) ? 0 : ax + 1; ay = (v.y != 0.0f) ? 0 : ay + 1;
        az = (v.z != 0.0f) ? 0 : az + 1; aw = (v.w != 0.0f) ? 0 : aw + 1;
    }
    int tend = t0 + seg_len; if (tend > T) tend = T;
    for (int t = t0; t < tend; ++t) {
        float4 v = x[(size_t)t * row4 + c];
        ax = (v.x != 0.0f) ? 0 : ax + 1; ay = (v.y != 0.0f) ? 0 : ay + 1;
        az = (v.z != 0.0f) ? 0 : az + 1; aw = (v.w != 0.0f) ? 0 : aw + 1;
        float4 o;
        o.x = (ax < d) ? 1.0f : 0.0f; o.y = (ay < d) ? 1.0f : 0.0f;
        o.z = (az < d) ? 1.0f : 0.0f; o.w = (aw < d) ? 1.0f : 0.0f;
        out[(size_t)t * row4 + c] = o;
    }
}

extern "C" void kernel_launch(void* const* d_in, const int* in_sizes, int n_in,
                              void* d_out, int out_size)
{
    const float* x = (const float*)d_in[0];
    const int* durp = (n_in > 1) ? (const int*)d_in[1] : nullptr;
    float* out = (float*)d_out;

    const int total = in_sizes[0];
    const int T = TDIM;
    const int row = total / T;
    const int row4 = row / 4;

    if ((row % 4 == 0) && (row4 <= MAXC) && (total == T * row)) {
        const int gx1 = (row4 + BLOCK1 - 1) / BLOCK1;
        psp_pass1<<<dim3(gx1, SEG), BLOCK1>>>((const uint4*)x, row4);

        // pass2 with programmatic dependent launch (overlap ramp with pass1 tail)
        cudaLaunchConfig_t cfg = {};
        cfg.gridDim  = dim3((row4 + BLOCK2 - 1) / BLOCK2, SEG, 1);
        cfg.blockDim = dim3(BLOCK2, 1, 1);
        cfg.dynamicSmemBytes = 0;
        cfg.stream = 0;
        cudaLaunchAttribute attr[1];
        attr[0].id = cudaLaunchAttributeProgrammaticStreamSerialization;
        attr[0].val.programmaticStreamSerializationAllowed = 1;
        cfg.attrs = attr;
        cfg.numAttrs = 1;
        cudaError_t e = cudaLaunchKernelEx(&cfg, psp_pass2,
                                           (float4*)out, (const int*)durp, row4);
        if (e != cudaSuccess) {   // PDL unavailable: plain launch
            psp_pass2<<<cfg.gridDim, cfg.blockDim>>>((float4*)out, durp, row4);
        }
    } else {
        const int seg = 8, seg_len = (T + seg - 1) / seg;
        dim3 grid((row4 + 127) / 128, seg);
        psp_scan_kernel<<<grid, 128>>>((const float4*)x, (float4*)out,
                                       durp, row4, T, seg_len);
    }
}

// round 16
// speedup vs baseline: 1.0199x; 1.0027x over previous
#include <cuda_runtime.h>
#include <cuda_bf16.h>
#include <cstdint>

// BinaryTimedPSP: out[t] = clip(causal boxcar sum width d, 0, 1).
// Binary spikes => out[t] = 1 iff any spike in [t-d+1, t].
//
// FINAL (converged): two-pass, phase-pure, PDL-overlapped. Sits at the
// measured DRAM floor: 256MiB read @~5.9 TB/s + 256MiB write @~6.1 TB/s
// + 16MiB L2-buffered mask round-trip + ~2us overhead ~= 92-95us.
// Isolated measurements: 8-deep forced LDG.128 batches beat 16-deep and
// rolling pipelines; BLOCK1=128 beats 256; fused read/write kernel loses
// (mixed streams run 5.2 TB/s aggregate); pass2 block size is noise.
//   P1: x -> per-(segment, component) 64-bit spike masks (read phase).
//   P2: masks (+ parallel bounded lookback, L2-hot) -> bits -> stores.

#define TDIM    2048
#define SEG     32
#define SEG_LEN 64
#define BLOCK1  128
#define BLOCK2  256
#define MAXC    8192          // max float4 column-groups (B*N/4)
#define BIGAGE  (1u << 20)

__device__ ulonglong4 g_mask[SEG * MAXC];   // 8 MiB

__device__ __forceinline__ unsigned long long window_or(unsigned long long s, unsigned d) {
    unsigned long long r = s;
    unsigned w = 1;
    while (w < d && w < 64u) {
        unsigned sh = d - w;
        if (sh > w) sh = w;
        r |= r << sh;
        w += sh;
    }
    return r;
}
__device__ __forceinline__ unsigned long long prefix_mask(unsigned len) {
    return (len >= 64u) ? ~0ull : ((1ull << len) - 1ull);
}
__device__ __forceinline__ unsigned load_d(const int* durp) {
    unsigned d = 100;
    if (durp) {
        int dv = *durp;
        if (dv > 0 && dv <= TDIM * 16) d = (unsigned)dv;
    }
    return d;
}

// v is 0x00000000 (0.0f) or 0x3F800000 (1.0f). Move bit 23 to bit t, masked.
__device__ __forceinline__ unsigned spikebit(unsigned v, int t) {
    unsigned sh = (t <= 23) ? (v >> (23 - t)) : (v << (t - 23));
    return sh & (1u << t);
}

__device__ __forceinline__ void ldg128_cs(const uint4* p,
                                          unsigned& a, unsigned& b,
                                          unsigned& c, unsigned& d) {
    asm volatile("ld.global.cs.v4.u32 {%0,%1,%2,%3}, [%4];"
                 : "=r"(a), "=r"(b), "=r"(c), "=r"(d) : "l"(p));
}

// ---- Pass 1: build spike masks (forced 8-deep load batches) ----
__global__ __launch_bounds__(BLOCK1) void psp_pass1(
    const uint4* __restrict__ x, int row4)
{
    const int c = blockIdx.x * BLOCK1 + threadIdx.x;
    const int s = blockIdx.y;
    if (c < row4) {
        const uint4* __restrict__ xp = x + (size_t)(s * SEG_LEN) * row4 + c;

        unsigned lo0 = 0, lo1 = 0, lo2 = 0, lo3 = 0;
        unsigned hi0 = 0, hi1 = 0, hi2 = 0, hi3 = 0;
        #pragma unroll
        for (int tb = 0; tb < SEG_LEN; tb += 8) {
            unsigned v[8][4];
            // 8 consecutive volatile loads: ptxas cannot sink/serialize them.
            #pragma unroll
            for (int k = 0; k < 8; ++k)
                ldg128_cs(&xp[(size_t)(tb + k) * row4],
                          v[k][0], v[k][1], v[k][2], v[k][3]);
            #pragma unroll
            for (int k = 0; k < 8; ++k) {
                const int t = tb + k;
                if (t < 32) {
                    lo0 |= spikebit(v[k][0], t);
                    lo1 |= spikebit(v[k][1], t);
                    lo2 |= spikebit(v[k][2], t);
                    lo3 |= spikebit(v[k][3], t);
                } else {
                    hi0 |= spikebit(v[k][0], t - 32);
                    hi1 |= spikebit(v[k][1], t - 32);
                    hi2 |= spikebit(v[k][2], t - 32);
                    hi3 |= spikebit(v[k][3], t - 32);
                }
            }
        }
        ulonglong4 m;
        m.x = (unsigned long long)lo0 | ((unsigned long long)hi0 << 32);
        m.y = (unsigned long long)lo1 | ((unsigned long long)hi1 << 32);
        m.z = (unsigned long long)lo2 | ((unsigned long long)hi2 << 32);
        m.w = (unsigned long long)lo3 | ((unsigned long long)hi3 << 32);
        g_mask[s * MAXC + c] = m;
    }
    // make mask stores visible, then let the dependent grid proceed
    __threadfence();
    cudaTriggerProgrammaticLaunchCompletion();
}

// ---- Pass 2: parallel bounded lookback + window-OR + streaming stores ----
__global__ __launch_bounds__(BLOCK2) void psp_pass2(
    float4* __restrict__ out, const int* __restrict__ durp, int row4)
{
    const int c = blockIdx.x * BLOCK2 + threadIdx.x;
    const int s = blockIdx.y;
    // prologue overlapped with pass1 (durp is harness input, stable pre-graph)
    const unsigned d = load_d(durp);
    float4* __restrict__ op = out + (size_t)(s * SEG_LEN) * row4 + c;

    cudaGridDependencySynchronize();
    if (c >= row4) return;

    // issue all (up to 3) mask loads in parallel: own + 2 predecessors
    ulonglong4 m = g_mask[s * MAXC + c];
    ulonglong4 pm1 = {0, 0, 0, 0}, pm2 = {0, 0, 0, 0};
    if (s >= 1)            pm1 = g_mask[(s - 1) * MAXC + c];
    if (s >= 2 && d > 65u) pm2 = g_mask[(s - 2) * MAXC + c];

    uint4 inc;
    inc.x = pm1.x ? (unsigned)__clzll(pm1.x) : (pm2.x ? 64u + (unsigned)__clzll(pm2.x) : BIGAGE);
    inc.y = pm1.y ? (unsigned)__clzll(pm1.y) : (pm2.y ? 64u + (unsigned)__clzll(pm2.y) : BIGAGE);
    inc.z = pm1.z ? (unsigned)__clzll(pm1.z) : (pm2.z ? 64u + (unsigned)__clzll(pm2.z) : BIGAGE);
    inc.w = pm1.w ? (unsigned)__clzll(pm1.w) : (pm2.w ? 64u + (unsigned)__clzll(pm2.w) : BIGAGE);

    if (d > 129u) {   // rare general case: continue lookback past 2 segments
        unsigned base = 128;
        for (int j = s - 3; j >= 0 && base + 1u < d; --j) {
            if (inc.x != BIGAGE && inc.y != BIGAGE && inc.z != BIGAGE && inc.w != BIGAGE)
                break;
            ulonglong4 pm = g_mask[j * MAXC + c];
            if (inc.x == BIGAGE && pm.x) inc.x = base + (unsigned)__clzll(pm.x);
            if (inc.y == BIGAGE && pm.y) inc.y = base + (unsigned)__clzll(pm.y);
            if (inc.z == BIGAGE && pm.z) inc.z = base + (unsigned)__clzll(pm.z);
            if (inc.w == BIGAGE && pm.w) inc.w = base + (unsigned)__clzll(pm.w);
            base += SEG_LEN;
        }
    }

    unsigned long long b0 = window_or(m.x, d);
    unsigned long long b1 = window_or(m.y, d);
    unsigned long long b2 = window_or(m.z, d);
    unsigned long long b3 = window_or(m.w, d);

    // prefix fix: bits t < min(first_spike, d-1-inc) forced to 1
    unsigned p0 = m.x ? (unsigned)(__ffsll((long long)m.x) - 1) : 64u;
    unsigned p1 = m.y ? (unsigned)(__ffsll((long long)m.y) - 1) : 64u;
    unsigned p2 = m.z ? (unsigned)(__ffsll((long long)m.z) - 1) : 64u;
    unsigned p3 = m.w ? (unsigned)(__ffsll((long long)m.w) - 1) : 64u;
    unsigned l0 = (inc.x + 1u < d) ? min(p0, d - 1u - inc.x) : 0u;
    unsigned l1 = (inc.y + 1u < d) ? min(p1, d - 1u - inc.y) : 0u;
    unsigned l2 = (inc.z + 1u < d) ? min(p2, d - 1u - inc.z) : 0u;
    unsigned l3 = (inc.w + 1u < d) ? min(p3, d - 1u - inc.w) : 0u;
    b0 |= prefix_mask(l0);
    b1 |= prefix_mask(l1);
    b2 |= prefix_mask(l2);
    b3 |= prefix_mask(l3);

    const unsigned a0 = (unsigned)b0, A0 = (unsigned)(b0 >> 32);
    const unsigned a1 = (unsigned)b1, A1 = (unsigned)(b1 >> 32);
    const unsigned a2 = (unsigned)b2, A2 = (unsigned)(b2 >> 32);
    const unsigned a3 = (unsigned)b3, A3 = (unsigned)(b3 >> 32);

    #pragma unroll
    for (int t = 0; t < 32; ++t) {
        float4 o;
        o.x = __uint_as_float((unsigned)(((int)(a0 << (31 - t))) >> 31) & 0x3F800000u);
        o.y = __uint_as_float((unsigned)(((int)(a1 << (31 - t))) >> 31) & 0x3F800000u);
        o.z = __uint_as_float((unsigned)(((int)(a2 << (31 - t))) >> 31) & 0x3F800000u);
        o.w = __uint_as_float((unsigned)(((int)(a3 << (31 - t))) >> 31) & 0x3F800000u);
        __stcs(&op[(size_t)t * row4], o);
    }
    #pragma unroll
    for (int t = 0; t < 32; ++t) {
        float4 o;
        o.x = __uint_as_float((unsigned)(((int)(A0 << (31 - t))) >> 31) & 0x3F800000u);
        o.y = __uint_as_float((unsigned)(((int)(A1 << (31 - t))) >> 31) & 0x3F800000u);
        o.z = __uint_as_float((unsigned)(((int)(A2 << (31 - t))) >> 31) & 0x3F800000u);
        o.w = __uint_as_float((unsigned)(((int)(A3 << (31 - t))) >> 31) & 0x3F800000u);
        __stcs(&op[(size_t)(t + 32) * row4], o);
    }
}

// ---- Fallback (odd shapes): halo scan ----
__global__ __launch_bounds__(128) void psp_scan_kernel(
    const float4* __restrict__ x, float4* __restrict__ out,
    const int* __restrict__ durp, int row4, int T, int seg_len)
{
    const int c = blockIdx.x * 128 + threadIdx.x;
    if (c >= row4) return;
    int d = 100;
    if (durp) { int dv = *durp; if (dv > 0 && dv <= T * 16) d = dv; }
    const int t0 = blockIdx.y * seg_len;
    int th = t0 - (d - 1); if (th < 0) th = 0;
    int ax = 1 << 28, ay = 1 << 28, az = 1 << 28, aw = 1 << 28;
    for (int t = th; t < t0; ++t) {
        float4 v = x[(size_t)t * row4 + c];
        ax = (v.x != 0.0f) ? 0 : ax + 1; ay = (v.y != 0.0f) ? 0 : ay + 1;
        az = (v.z != 0.0f) ? 0 : az + 1; aw = (v.w != 0.0f) ? 0 : aw + 1;
    }
    int tend = t0 + seg_len; if (tend > T) tend = T;
    for (int t = t0; t < tend; ++t) {
        float4 v = x[(size_t)t * row4 + c];
        ax = (v.x != 0.0f) ? 0 : ax + 1; ay = (v.y != 0.0f) ? 0 : ay + 1;
        az = (v.z != 0.0f) ? 0 : az + 1; aw = (v.w != 0.0f) ? 0 : aw + 1;
        float4 o;
        o.x = (ax < d) ? 1.0f : 0.0f; o.y = (ay < d) ? 1.0f : 0.0f;
        o.z = (az < d) ? 1.0f : 0.0f; o.w = (aw < d) ? 1.0f : 0.0f;
        out[(size_t)t * row4 + c] = o;
    }
}

extern "C" void kernel_launch(void* const* d_in, const int* in_sizes, int n_in,
                              void* d_out, int out_size)
{
    const float* x = (const float*)d_in[0];
    const int* durp = (n_in > 1) ? (const int*)d_in[1] : nullptr;
    float* out = (float*)d_out;

    const int total = in_sizes[0];
    const int T = TDIM;
    const int row = total / T;
    const int row4 = row / 4;

    if ((row % 4 == 0) && (row4 <= MAXC) && (total == T * row)) {
        const int gx1 = (row4 + BLOCK1 - 1) / BLOCK1;
        psp_pass1<<<dim3(gx1, SEG), BLOCK1>>>((const uint4*)x, row4);

        // pass2 with programmatic dependent launch (overlap ramp with pass1 tail)
        cudaLaunchConfig_t cfg = {};
        cfg.gridDim  = dim3((row4 + BLOCK2 - 1) / BLOCK2, SEG, 1);
        cfg.blockDim = dim3(BLOCK2, 1, 1);
        cfg.dynamicSmemBytes = 0;
        cfg.stream = 0;
        cudaLaunchAttribute attr[1];
        attr[0].id = cudaLaunchAttributeProgrammaticStreamSerialization;
        attr[0].val.programmaticStreamSerializationAllowed = 1;
        cfg.attrs = attr;
        cfg.numAttrs = 1;
        cudaError_t e = cudaLaunchKernelEx(&cfg, psp_pass2,
                                           (float4*)out, (const int*)durp, row4);
        if (e != cudaSuccess) {   // PDL unavailable: plain launch
            psp_pass2<<<cfg.gridDim, cfg.blockDim>>>((float4*)out, durp, row4);
        }
    } else {
        const int seg = 8, seg_len = (T + seg - 1) / seg;
        dim3 grid((row4 + 127) / 128, seg);
        psp_scan_kernel<<<grid, 128>>>((const float4*)x, (float4*)out,
                                       durp, row4, T, seg_len);
    }
}